// round 14
// baseline (speedup 1.0000x reference)
#include <cuda_runtime.h>
#include <cstdint>

#define B_ 8
#define C_ 16
#define H_ 224
#define W_ 224
#define T_ 8
#define N_ 5
#define NEGV (-1e30f)
#define NTOT (B_*C_*H_*W_)
#define FULLW 0xffffffffu

// Scratch: xv = log1p(relu(x)); padded TWO rows for prefetch distance 2.
__device__ float g_xv[NTOT + 2 * W_];

__global__ void xv_kernel(const float* __restrict__ x) {
    int n4 = NTOT / 4;
    for (int i = blockIdx.x * blockDim.x + threadIdx.x; i < n4;
         i += gridDim.x * blockDim.x) {
        float4 v = reinterpret_cast<const float4*>(x)[i];
        v.x = log1pf(fmaxf(v.x, 0.f));
        v.y = log1pf(fmaxf(v.y, 0.f));
        v.z = log1pf(fmaxf(v.z, 0.f));
        v.w = log1pf(fmaxf(v.w, 0.f));
        reinterpret_cast<float4*>(g_xv)[i] = v;
    }
}

struct Forest { int par[T_][N_]; };

// ============================================================================
// Compile-time plan: alphas factor out of prefix-max (P(f+c)=P(f)+c); nodes
// with equal subtree shapes share one scan slot.
// ============================================================================
struct Plan {
    int ns;
    int childCnt[4][4];
    int rootCnt[4];
};

__host__ __device__ constexpr Plan makePlan(int P2, int P3, int P4) {
    Plan pl{};
    int par[5] = {-1, 0, P2, P3, P4};
    int regA[8] = {}, regB[8] = {}, regC[8] = {};
    int nreg = 1;
    regA[0] = -1; regB[0] = -1; regC[0] = -1;
    int shape[5] = {0, 0, 0, 0, 0};
    for (int i = 4; i >= 1; i--) {
        int k[3] = {-1, -1, -1};
        int nk = 0;
        for (int m = i + 1; m <= 4; m++)
            if (par[m] == i) k[nk++] = shape[m];
        for (int a = 0; a < 3; a++)
            for (int b = a + 1; b < 3; b++)
                if (k[b] > k[a]) { int tm = k[a]; k[a] = k[b]; k[b] = tm; }
        int id = -1;
        for (int r = 0; r < nreg; r++)
            if (regA[r] == k[0] && regB[r] == k[1] && regC[r] == k[2]) id = r;
        if (id < 0) {
            regA[nreg] = k[0]; regB[nreg] = k[1]; regC[nreg] = k[2];
            id = nreg++;
        }
        shape[i] = id;
    }
    int slotOfShape[8] = {-1, -1, -1, -1, -1, -1, -1, -1};
    int slotOfNode[5] = {0, 0, 0, 0, 0};
    pl.ns = 0;
    for (int i = 4; i >= 1; i--) {
        int s = shape[i];
        if (slotOfShape[s] < 0) {
            int sl = pl.ns;
            pl.ns = pl.ns + 1;
            slotOfShape[s] = sl;
            for (int m = i + 1; m <= 4; m++)
                if (par[m] == i) pl.childCnt[sl][slotOfNode[m]]++;
        }
        slotOfNode[i] = slotOfShape[s];
    }
    for (int m = 1; m <= 4; m++)
        if (par[m] == 0) pl.rootCnt[slotOfNode[m]]++;
    return pl;
}

// dst[k] += C * shifted(M)[k]; chunk width 4; shifted = (Bnd at k==0, M[k-1]).
// Uses M[0..2] only (M[3] is dead state).
template <int CNT>
__device__ __forceinline__ void add_shift4(float dst[4], const float Mc[4],
                                           float bndc) {
    if (CNT == 1) {
        dst[0] += bndc;
#pragma unroll
        for (int k = 1; k < 4; k++) dst[k] += Mc[k - 1];
    } else {
        dst[0] = fmaf((float)CNT, bndc, dst[0]);
#pragma unroll
        for (int k = 1; k < 4; k++) dst[k] = fmaf((float)CNT, Mc[k - 1], dst[k]);
    }
}

// One plane split across TWO warps (56 chunks x 4 cols). Both warps process
// the same row; the cross-chunk exclusive term e is exchanged via smem and
// consumed one row later (exactly, by max idempotence) — no serial handoff.
template <int P2, int P3, int P4>
__device__ __forceinline__ float tree_block(const float* __restrict__ rowp,
                                            int warp, int lane, bool act,
                                            float (*s_tot)[56],
                                            float (*s_pref)[56]) {
    constexpr Plan pl = makePlan(P2, P3, P4);
    constexpr int NS = pl.ns;
    const int chunk = warp * 28 + lane;   // 0..55 for active threads

    float M[NS][4];
    float Bnd[NS], e[NS];
#pragma unroll
    for (int s = 0; s < NS; s++) {
        Bnd[s] = NEGV;
        e[s] = NEGV;
#pragma unroll
        for (int k = 0; k < 4; k++) M[s][k] = NEGV;
    }
    float runmax = NEGV;

    // prefetch distance 2 (one float4 per thread per row)
    float4 cur, p1;
    if (act) {
        cur = *reinterpret_cast<const float4*>(rowp);
        p1  = *reinterpret_cast<const float4*>(rowp + W_);
    } else {
        cur = make_float4(NEGV, NEGV, NEGV, NEGV);
        p1 = cur;
    }
    rowp += W_;

    // scanner-slot assignment: lanes 0,1 of each warp; slot = warp*2+lane.
    const int sidx = (lane < 2) ? (warp * 2 + lane) : 99;

#pragma unroll 2
    for (int h = 0; h < H_; h++) {
        const float* nrp = rowp + W_;
        float4 p2;
        if (act) p2 = *reinterpret_cast<const float4*>(nrp);
        else     p2 = make_float4(NEGV, NEGV, NEGV, NEGV);

        // ---- fold previous row's cross-chunk term (deferred, exact) ----
#pragma unroll
        for (int s = 0; s < NS; s++) {
            Bnd[s] = fmaxf(Bnd[s], e[s]);
#pragma unroll
            for (int k = 0; k < 3; k++) M[s][k] = fmaxf(M[s][k], e[s]);
        }

        float xv[4] = {cur.x, cur.y, cur.z, cur.w};

        // ---- root value + plane max (state through row h-1) ----
        {
            float r[4] = {xv[0], xv[1], xv[2], xv[3]};
#pragma unroll
            for (int s = 0; s < NS; s++) {
                if (pl.rootCnt[s] == 1) add_shift4<1>(r, M[s], Bnd[s]);
                else if (pl.rootCnt[s] == 2) add_shift4<2>(r, M[s], Bnd[s]);
                else if (pl.rootCnt[s] == 3) add_shift4<3>(r, M[s], Bnd[s]);
                else if (pl.rootCnt[s] == 4) add_shift4<4>(r, M[s], Bnd[s]);
            }
#pragma unroll
            for (int k = 0; k < 4; k++) runmax = fmaxf(runmax, r[k]);
        }

        // ---- build accs for all slots (state through row h-1) ----
        float acc[NS][4];
#pragma unroll
        for (int s = 0; s < NS; s++) {
#pragma unroll
            for (int k = 0; k < 4; k++) acc[s][k] = xv[k];
#pragma unroll
            for (int cs = 0; cs < NS; cs++) {
                if (pl.childCnt[s][cs] == 1) add_shift4<1>(acc[s], M[cs], Bnd[cs]);
                else if (pl.childCnt[s][cs] == 2) add_shift4<2>(acc[s], M[cs], Bnd[cs]);
                else if (pl.childCnt[s][cs] == 3) add_shift4<3>(acc[s], M[cs], Bnd[cs]);
            }
        }

        // ---- chunk prefix (3 fmax per slot) + merge local into M[0..2] ----
#pragma unroll
        for (int s = 0; s < NS; s++) {
            acc[s][1] = fmaxf(acc[s][1], acc[s][0]);
            acc[s][2] = fmaxf(acc[s][2], acc[s][1]);
            acc[s][3] = fmaxf(acc[s][3], acc[s][2]);
#pragma unroll
            for (int k = 0; k < 3; k++) M[s][k] = fmaxf(M[s][k], acc[s][k]);
        }

        // ---- publish row totals ----
        if (act) {
#pragma unroll
            for (int s = 0; s < NS; s++) s_tot[s][chunk] = acc[s][3];
        }
        __syncthreads();   // (A) totals visible

        // ---- scanner threads: 56-wide grouped exclusive prefix ----
        if (sidx < NS) {
            const float4* t4 = reinterpret_cast<const float4*>(s_tot[sidx]);
            float4* o4 = reinterpret_cast<float4*>(s_pref[sidx]);
            float4 T[14];
#pragma unroll
            for (int q = 0; q < 14; q++) T[q] = t4[q];
            float i1[14], i2[14], i3[14];
#pragma unroll
            for (int q = 0; q < 14; q++) {
                i1[q] = fmaxf(T[q].x, T[q].y);
                i2[q] = fmaxf(i1[q], T[q].z);
                i3[q] = fmaxf(i2[q], T[q].w);
            }
            float G[14];
            G[0] = NEGV;
#pragma unroll
            for (int q = 1; q < 14; q++) G[q] = fmaxf(G[q - 1], i3[q - 1]);
#pragma unroll
            for (int q = 0; q < 14; q++) {
                o4[q] = make_float4(G[q],
                                    fmaxf(G[q], T[q].x),
                                    fmaxf(G[q], i1[q]),
                                    fmaxf(G[q], i2[q]));
            }
        }
        __syncthreads();   // (B) prefixes visible

#pragma unroll
        for (int s = 0; s < NS; s++) {
            float ev = s_pref[s][act ? chunk : 0];
            e[s] = act ? ev : NEGV;
        }

        cur = p1; p1 = p2;
        rowp = nrp;
    }

#pragma unroll
    for (int d = 16; d; d >>= 1)
        runmax = fmaxf(runmax, __shfl_xor_sync(FULLW, runmax, d));
    return runmax;
}

__global__ void __launch_bounds__(64)
forest_kernel(const float* __restrict__ alphas, float* __restrict__ out, Forest f) {
    __shared__ __align__(16) float s_tot[4][56];
    __shared__ __align__(16) float s_pref[4][56];
    __shared__ float s_red[2];

    int blk = blockIdx.x;
    int t = blk & 7;            // trees interleaved across SMs
    int c = (blk >> 3) & 15;
    int b = blk >> 7;
    int warp = threadIdx.x >> 5;
    int lane = threadIdx.x & 31;
    const bool act = lane < 28;

    const float* plane = g_xv + (size_t)(b * C_ + c) * (H_ * W_);
    const float* rowp = plane + (warp * 28 + lane) * 4;

    const int p2 = f.par[t][2], p3 = f.par[t][3], p4 = f.par[t][4];
    int code = p2 * 12 + p3 * 4 + p4;

    float res = NEGV;
    switch (code) {
#define CASE_T(P2V, P3V, P4V)                                                  \
    case (P2V * 12 + P3V * 4 + P4V):                                           \
        res = tree_block<P2V, P3V, P4V>(rowp, warp, lane, act, s_tot, s_pref); \
        break;
        CASE_T(0,0,0) CASE_T(0,0,1) CASE_T(0,0,2) CASE_T(0,0,3)
        CASE_T(0,1,0) CASE_T(0,1,1) CASE_T(0,1,2) CASE_T(0,1,3)
        CASE_T(0,2,0) CASE_T(0,2,1) CASE_T(0,2,2) CASE_T(0,2,3)
        CASE_T(1,0,0) CASE_T(1,0,1) CASE_T(1,0,2) CASE_T(1,0,3)
        CASE_T(1,1,0) CASE_T(1,1,1) CASE_T(1,1,2) CASE_T(1,1,3)
        CASE_T(1,2,0) CASE_T(1,2,1) CASE_T(1,2,2) CASE_T(1,2,3)
#undef CASE_T
        default: break;
    }

    if (lane == 0) s_red[warp] = res;
    __syncthreads();
    if (threadIdx.x == 0) {
        float m = fmaxf(s_red[0], s_red[1]);
        float K = 0.f;
#pragma unroll
        for (int i = 0; i < N_; i++) K += alphas[(t * N_ + i) * C_ + c];
        out[(b * T_ + t) * C_ + c] = expm1f(m + K);
    }
}

// ============================================================================
// Host: exact replication of np.random.default_rng(0) draws used by
// make_forest(): SeedSequence(0) -> PCG64 (XSL-RR 128/64) -> Generator
// .integers(0, i) (Lemire, buffered 32-bit path) for i = 1..4 per tree.
// ============================================================================

static inline uint32_t hashmix_(uint32_t v, uint32_t* hc) {
    v ^= *hc;
    *hc *= 0x931e8875u;   // MULT_A
    v *= *hc;
    v ^= v >> 16;
    return v;
}
static inline uint32_t mix_(uint32_t x, uint32_t y) {
    uint32_t r = x * 0xca01f9ddu - y * 0x4973f715u;  // MIX_MULT_L/R
    r ^= r >> 16;
    return r;
}

static void compute_forest(Forest* f) {
    uint32_t pool[4];
    uint32_t hc = 0x43b0d7e5u;  // INIT_A
    for (int i = 0; i < 4; i++) pool[i] = hashmix_(0u, &hc);
    for (int s = 0; s < 4; s++)
        for (int d = 0; d < 4; d++)
            if (s != d) pool[d] = mix_(pool[d], hashmix_(pool[s], &hc));

    uint32_t hb = 0x8b51f9ddu;  // INIT_B
    uint32_t w32[8];
    for (int i = 0; i < 8; i++) {
        uint32_t dv = pool[i & 3];
        dv ^= hb;
        hb *= 0x58f38dedu;  // MULT_B
        dv *= hb;
        dv ^= dv >> 16;
        w32[i] = dv;
    }
    uint64_t val[4];
    for (int i = 0; i < 4; i++)
        val[i] = (uint64_t)w32[2 * i] | ((uint64_t)w32[2 * i + 1] << 32);

    typedef unsigned __int128 u128;
    const u128 MULT = ((u128)2549297995355413924ULL << 64) | 4865540595714422341ULL;
    u128 initstate = ((u128)val[0] << 64) | (u128)val[1];
    u128 inc = (((((u128)val[2] << 64) | (u128)val[3])) << 1) | 1;
    u128 state = inc;
    state += initstate;
    state = state * MULT + inc;

    int has32 = 0;
    uint32_t cached = 0;

    for (int t = 0; t < T_; t++) {
        f->par[t][0] = -1;
        f->par[t][1] = 0;  // integers(0,1): rng==0, no draw consumed
        for (int i = 2; i < N_; i++) {
            uint32_t rng = (uint32_t)i - 1u;
            uint32_t rng_excl = rng + 1u;
            uint64_t m;
            uint32_t leftover;
            for (;;) {
                uint32_t r32;
                if (has32) {
                    has32 = 0;
                    r32 = cached;
                } else {
                    state = state * MULT + inc;
                    uint64_t hi = (uint64_t)(state >> 64);
                    uint64_t lo = (uint64_t)state;
                    unsigned rot = (unsigned)(uint64_t)(state >> 122);
                    uint64_t x = hi ^ lo;
                    uint64_t o = (x >> rot) | (x << ((64u - rot) & 63u));
                    has32 = 1;
                    cached = (uint32_t)(o >> 32);
                    r32 = (uint32_t)o;
                }
                m = (uint64_t)r32 * (uint64_t)rng_excl;
                leftover = (uint32_t)m;
                if (leftover >= rng_excl) break;
                uint32_t thr = (0xFFFFFFFFu - rng) % rng_excl;
                if (leftover >= thr) break;
            }
            f->par[t][i] = (int)(uint32_t)(m >> 32);
        }
    }
}

extern "C" void kernel_launch(void* const* d_in, const int* in_sizes, int n_in,
                              void* d_out, int out_size) {
    const float* x = (const float*)d_in[0];
    const float* alphas = (const float*)d_in[1];
    float* out = (float*)d_out;

    Forest f;
    compute_forest(&f);

    xv_kernel<<<NTOT / 4 / 256, 256>>>(x);
    forest_kernel<<<B_ * C_ * T_, 64>>>(alphas, out, f);
}

// round 15
// speedup vs baseline: 2.2285x; 2.2285x over previous
#include <cuda_runtime.h>
#include <cstdint>

#define B_ 8
#define C_ 16
#define H_ 224
#define W_ 224
#define T_ 8
#define N_ 5
#define NEGV (-1e30f)
#define NTOT (B_*C_*H_*W_)
#define FULLW 0xffffffffu

// Scratch: xv = log1p(relu(x)); padded TWO rows for prefetch distance 2.
__device__ float g_xv[NTOT + 2 * W_];

__global__ void xv_kernel(const float* __restrict__ x) {
    int n4 = NTOT / 4;
    for (int i = blockIdx.x * blockDim.x + threadIdx.x; i < n4;
         i += gridDim.x * blockDim.x) {
        float4 v = reinterpret_cast<const float4*>(x)[i];
        v.x = log1pf(fmaxf(v.x, 0.f));
        v.y = log1pf(fmaxf(v.y, 0.f));
        v.z = log1pf(fmaxf(v.z, 0.f));
        v.w = log1pf(fmaxf(v.w, 0.f));
        reinterpret_cast<float4*>(g_xv)[i] = v;
    }
}

struct Forest { int par[T_][N_]; };

// ============================================================================
// Compile-time plan: alphas factor out of prefix-max (P(f+c)=P(f)+c); nodes
// with equal subtree shapes share one scan slot.
// ============================================================================
struct Plan {
    int ns;
    int childCnt[4][4];
    int rootCnt[4];
};

__host__ __device__ constexpr Plan makePlan(int P2, int P3, int P4) {
    Plan pl{};
    int par[5] = {-1, 0, P2, P3, P4};
    int regA[8] = {}, regB[8] = {}, regC[8] = {};
    int nreg = 1;
    regA[0] = -1; regB[0] = -1; regC[0] = -1;
    int shape[5] = {0, 0, 0, 0, 0};
    for (int i = 4; i >= 1; i--) {
        int k[3] = {-1, -1, -1};
        int nk = 0;
        for (int m = i + 1; m <= 4; m++)
            if (par[m] == i) k[nk++] = shape[m];
        for (int a = 0; a < 3; a++)
            for (int b = a + 1; b < 3; b++)
                if (k[b] > k[a]) { int tm = k[a]; k[a] = k[b]; k[b] = tm; }
        int id = -1;
        for (int r = 0; r < nreg; r++)
            if (regA[r] == k[0] && regB[r] == k[1] && regC[r] == k[2]) id = r;
        if (id < 0) {
            regA[nreg] = k[0]; regB[nreg] = k[1]; regC[nreg] = k[2];
            id = nreg++;
        }
        shape[i] = id;
    }
    int slotOfShape[8] = {-1, -1, -1, -1, -1, -1, -1, -1};
    int slotOfNode[5] = {0, 0, 0, 0, 0};
    pl.ns = 0;
    for (int i = 4; i >= 1; i--) {
        int s = shape[i];
        if (slotOfShape[s] < 0) {
            int sl = pl.ns;
            pl.ns = pl.ns + 1;
            slotOfShape[s] = sl;
            for (int m = i + 1; m <= 4; m++)
                if (par[m] == i) pl.childCnt[sl][slotOfNode[m]]++;
        }
        slotOfNode[i] = slotOfShape[s];
    }
    for (int m = 1; m <= 4; m++)
        if (par[m] == 0) pl.rootCnt[slotOfNode[m]]++;
    return pl;
}

// dst[k] += C * shifted(M)[k]; shifted = (Bnd at k==0, M[k-1] else).
// Uses M[0..6]. Multiplier routed through the opaque runtime `one` so the
// adds compile to FFMA (fma pipe) instead of FADD (alu pipe) — pipe balance.
template <int CNT>
__device__ __forceinline__ void add_shift(float dst[8], const float Mc[8],
                                          float bndc, float one) {
    float m = (float)CNT * one;
    dst[0] = fmaf(m, bndc, dst[0]);
#pragma unroll
    for (int k = 1; k < 8; k++) dst[k] = fmaf(m, Mc[k - 1], dst[k]);
}

template <int P2, int P3, int P4>
__device__ __forceinline__ float tree_warp(const float* __restrict__ rowp,
                                           int lane, bool act, float one) {
    constexpr Plan pl = makePlan(P2, P3, P4);
    constexpr int NS = pl.ns;

    // M[s][0..6]: in-lane 2D cummax state; cross-lane term folded LAZILY:
    // e[s] = row (h-1)'s exclusive lane-max, folded at the start of row h.
    // Bnd[s] = full cross-lane boundary (max of e's). The butterfly scan
    // producing e is DEFERRED (consumed next row), so its 5-step SHFL
    // latency chain sits off the per-row critical path.
    float M[NS][8];
    float Bnd[NS], e[NS];
#pragma unroll
    for (int s = 0; s < NS; s++) {
        Bnd[s] = NEGV;
        e[s] = NEGV;
#pragma unroll
        for (int k = 0; k < 8; k++) M[s][k] = NEGV;
    }
    float runmax = NEGV;

    // Triple-buffered row loads: prefetch distance 2.
    float4 c0, c1, p10, p11;
    if (act) {
        c0  = *reinterpret_cast<const float4*>(rowp);
        c1  = *reinterpret_cast<const float4*>(rowp + 4);
        p10 = *reinterpret_cast<const float4*>(rowp + W_);
        p11 = *reinterpret_cast<const float4*>(rowp + W_ + 4);
    } else {
        c0 = make_float4(NEGV, NEGV, NEGV, NEGV);
        c1 = c0; p10 = c0; p11 = c0;
    }
    rowp += W_;  // rowp points at row h+1 when processing row h

#pragma unroll 2
    for (int h = 0; h < H_; h++) {
        const float* nrp = rowp + W_;
        float4 p20, p21;
        if (act) {
            p20 = *reinterpret_cast<const float4*>(nrp);
            p21 = *reinterpret_cast<const float4*>(nrp + 4);
        } else { p20 = make_float4(NEGV, NEGV, NEGV, NEGV); p21 = p20; }

        // ---- fold previous row's cross-lane term (deferred merge) ----
#pragma unroll
        for (int s = 0; s < NS; s++) {
            Bnd[s] = fmaxf(Bnd[s], e[s]);
#pragma unroll
            for (int k = 0; k < 7; k++) M[s][k] = fmaxf(M[s][k], e[s]);
        }

        float xv[8] = {c0.x, c0.y, c0.z, c0.w, c1.x, c1.y, c1.z, c1.w};

        // ---- root value + plane max (state through row h-1) ----
        {
            float r[8];
#pragma unroll
            for (int k = 0; k < 8; k++) r[k] = xv[k];
#pragma unroll
            for (int s = 0; s < NS; s++) {
                if (pl.rootCnt[s] == 1) add_shift<1>(r, M[s], Bnd[s], one);
                else if (pl.rootCnt[s] == 2) add_shift<2>(r, M[s], Bnd[s], one);
                else if (pl.rootCnt[s] == 3) add_shift<3>(r, M[s], Bnd[s], one);
                else if (pl.rootCnt[s] == 4) add_shift<4>(r, M[s], Bnd[s], one);
            }
#pragma unroll
            for (int k = 0; k < 8; k++) runmax = fmaxf(runmax, r[k]);
        }

        // ---- build accs for all slots (state through row h-1) ----
        float acc[NS][8];
#pragma unroll
        for (int s = 0; s < NS; s++) {
#pragma unroll
            for (int k = 0; k < 8; k++) acc[s][k] = xv[k];
#pragma unroll
            for (int cs = 0; cs < NS; cs++) {
                if (pl.childCnt[s][cs] == 1) add_shift<1>(acc[s], M[cs], Bnd[cs], one);
                else if (pl.childCnt[s][cs] == 2) add_shift<2>(acc[s], M[cs], Bnd[cs], one);
                else if (pl.childCnt[s][cs] == 3) add_shift<3>(acc[s], M[cs], Bnd[cs], one);
            }
        }

        // ---- chunk prefix per slot (interleaved fmax chains) ----
#pragma unroll
        for (int s = 0; s < NS; s++)
#pragma unroll
            for (int k = 1; k < 8; k++)
                acc[s][k] = fmaxf(acc[s][k], acc[s][k - 1]);

        // ---- merge local part into M (k = 0..6; M[7] is dead state) ----
#pragma unroll
        for (int s = 0; s < NS; s++)
#pragma unroll
            for (int k = 0; k < 7; k++)
                M[s][k] = fmaxf(M[s][k], acc[s][k]);

        // ---- cross-lane exclusive scan: deferred butterfly (no smem,
        //      no syncwarp). ex = exclusive max over chunks < lane.
        //      Inactive lanes carry NEGV throughout — harmless. ----
        {
            float ex[NS];
#pragma unroll
            for (int s = 0; s < NS; s++) {
                ex[s] = __shfl_up_sync(FULLW, acc[s][7], 1);
            }
            if (lane == 0) {
#pragma unroll
                for (int s = 0; s < NS; s++) ex[s] = NEGV;
            }
#pragma unroll
            for (int d = 1; d < 32; d <<= 1) {
                float o[NS];
#pragma unroll
                for (int s = 0; s < NS; s++)
                    o[s] = __shfl_up_sync(FULLW, ex[s], d);  // self if lane<d
#pragma unroll
                for (int s = 0; s < NS; s++) ex[s] = fmaxf(ex[s], o[s]);
            }
#pragma unroll
            for (int s = 0; s < NS; s++) e[s] = ex[s];
        }

        // rotate buffers
        c0 = p10; c1 = p11;
        p10 = p20; p11 = p21;
        rowp = nrp;
    }

#pragma unroll
    for (int d = 16; d; d >>= 1)
        runmax = fmaxf(runmax, __shfl_xor_sync(FULLW, runmax, d));
    return runmax;
}

__global__ void __launch_bounds__(32)
forest_kernel(const float* __restrict__ alphas, float* __restrict__ out,
              Forest f, float one) {
    int blk = blockIdx.x;
    int t = blk & 7;            // trees interleaved across SMs
    int c = (blk >> 3) & 15;
    int b = blk >> 7;
    int lane = threadIdx.x;
    const bool act = lane < 28;

    const float* plane = g_xv + (size_t)(b * C_ + c) * (H_ * W_);
    const float* rowp = plane + lane * 8;

    const int p2 = f.par[t][2], p3 = f.par[t][3], p4 = f.par[t][4];
    int code = p2 * 12 + p3 * 4 + p4;

    float res = NEGV;
    switch (code) {
#define CASE_T(P2V, P3V, P4V)                                                  \
    case (P2V * 12 + P3V * 4 + P4V):                                           \
        res = tree_warp<P2V, P3V, P4V>(rowp, lane, act, one);                  \
        break;
        CASE_T(0,0,0) CASE_T(0,0,1) CASE_T(0,0,2) CASE_T(0,0,3)
        CASE_T(0,1,0) CASE_T(0,1,1) CASE_T(0,1,2) CASE_T(0,1,3)
        CASE_T(0,2,0) CASE_T(0,2,1) CASE_T(0,2,2) CASE_T(0,2,3)
        CASE_T(1,0,0) CASE_T(1,0,1) CASE_T(1,0,2) CASE_T(1,0,3)
        CASE_T(1,1,0) CASE_T(1,1,1) CASE_T(1,1,2) CASE_T(1,1,3)
        CASE_T(1,2,0) CASE_T(1,2,1) CASE_T(1,2,2) CASE_T(1,2,3)
#undef CASE_T
        default: break;
    }

    if (lane == 0) {
        float K = 0.f;
#pragma unroll
        for (int i = 0; i < N_; i++) K += alphas[(t * N_ + i) * C_ + c];
        out[(b * T_ + t) * C_ + c] = expm1f(res + K);
    }
}

// ============================================================================
// Host: exact replication of np.random.default_rng(0) draws used by
// make_forest(): SeedSequence(0) -> PCG64 (XSL-RR 128/64) -> Generator
// .integers(0, i) (Lemire, buffered 32-bit path) for i = 1..4 per tree.
// ============================================================================

static inline uint32_t hashmix_(uint32_t v, uint32_t* hc) {
    v ^= *hc;
    *hc *= 0x931e8875u;   // MULT_A
    v *= *hc;
    v ^= v >> 16;
    return v;
}
static inline uint32_t mix_(uint32_t x, uint32_t y) {
    uint32_t r = x * 0xca01f9ddu - y * 0x4973f715u;  // MIX_MULT_L/R
    r ^= r >> 16;
    return r;
}

static void compute_forest(Forest* f) {
    uint32_t pool[4];
    uint32_t hc = 0x43b0d7e5u;  // INIT_A
    for (int i = 0; i < 4; i++) pool[i] = hashmix_(0u, &hc);
    for (int s = 0; s < 4; s++)
        for (int d = 0; d < 4; d++)
            if (s != d) pool[d] = mix_(pool[d], hashmix_(pool[s], &hc));

    uint32_t hb = 0x8b51f9ddu;  // INIT_B
    uint32_t w32[8];
    for (int i = 0; i < 8; i++) {
        uint32_t dv = pool[i & 3];
        dv ^= hb;
        hb *= 0x58f38dedu;  // MULT_B
        dv *= hb;
        dv ^= dv >> 16;
        w32[i] = dv;
    }
    uint64_t val[4];
    for (int i = 0; i < 4; i++)
        val[i] = (uint64_t)w32[2 * i] | ((uint64_t)w32[2 * i + 1] << 32);

    typedef unsigned __int128 u128;
    const u128 MULT = ((u128)2549297995355413924ULL << 64) | 4865540595714422341ULL;
    u128 initstate = ((u128)val[0] << 64) | (u128)val[1];
    u128 inc = (((((u128)val[2] << 64) | (u128)val[3])) << 1) | 1;
    u128 state = inc;
    state += initstate;
    state = state * MULT + inc;

    int has32 = 0;
    uint32_t cached = 0;

    for (int t = 0; t < T_; t++) {
        f->par[t][0] = -1;
        f->par[t][1] = 0;  // integers(0,1): rng==0, no draw consumed
        for (int i = 2; i < N_; i++) {
            uint32_t rng = (uint32_t)i - 1u;
            uint32_t rng_excl = rng + 1u;
            uint64_t m;
            uint32_t leftover;
            for (;;) {
                uint32_t r32;
                if (has32) {
                    has32 = 0;
                    r32 = cached;
                } else {
                    state = state * MULT + inc;
                    uint64_t hi = (uint64_t)(state >> 64);
                    uint64_t lo = (uint64_t)state;
                    unsigned rot = (unsigned)(uint64_t)(state >> 122);
                    uint64_t x = hi ^ lo;
                    uint64_t o = (x >> rot) | (x << ((64u - rot) & 63u));
                    has32 = 1;
                    cached = (uint32_t)(o >> 32);
                    r32 = (uint32_t)o;
                }
                m = (uint64_t)r32 * (uint64_t)rng_excl;
                leftover = (uint32_t)m;
                if (leftover >= rng_excl) break;
                uint32_t thr = (0xFFFFFFFFu - rng) % rng_excl;
                if (leftover >= thr) break;
            }
            f->par[t][i] = (int)(uint32_t)(m >> 32);
        }
    }
}

extern "C" void kernel_launch(void* const* d_in, const int* in_sizes, int n_in,
                              void* d_out, int out_size) {
    const float* x = (const float*)d_in[0];
    const float* alphas = (const float*)d_in[1];
    float* out = (float*)d_out;

    Forest f;
    compute_forest(&f);

    xv_kernel<<<NTOT / 4 / 256, 256>>>(x);
    forest_kernel<<<B_ * C_ * T_, 32>>>(alphas, out, f, 1.0f);
}